// round 4
// baseline (speedup 1.0000x reference)
#include <cuda_runtime.h>

#define DIMC 128
#define TM   64
#define SWT  132   // W^T row stride (mult of 4 -> 16B-aligned LDS.128; 4-way STS conflict, one-time)
#define SAT  68    // A^T row stride (mult of 4 -> 16B-aligned LDS.128; 4-way STS conflict, one-time)
#define NNODES 50000

// Scratch (no cudaMalloc allowed)
__device__ float g_h[(size_t)NNODES * DIMC];
__device__ float g_n[(size_t)NNODES * DIMC];

#define FMA_F32X2(d, a, b) \
    asm("fma.rn.f32x2 %0, %1, %2, %0;" : "+l"(d) : "l"(a), "l"(b))
#define PACK_DUP_F32X2(d, x) \
    asm("mov.b64 %0, {%1, %1};" : "=l"(d) : "f"(x))
#define UNPACK_F32X2(lo, hi, v) \
    asm("mov.b64 {%0, %1}, %2;" : "=f"(lo), "=f"(hi) : "l"(v))

// C[M,128] = relu(A[M,128] @ W^T + bias); optionally also n_init = 1 + eps*C
__global__ __launch_bounds__(256, 2) void gemm_relu_kernel(
    const float* __restrict__ A, const float* __restrict__ W,
    const float* __restrict__ bias, float* __restrict__ out,
    float* __restrict__ n_init, const float* __restrict__ eps, int M)
{
    extern __shared__ float smem[];
    float* Wt  = smem;               // W^T: [k=128][SWT]  Wt[k*SWT+col] = W[col*128+k]
    float* AsT = smem + DIMC * SWT;  // A^T tile: [k=128][SAT]  AsT[k*SAT+r] = A[(row0+r)*128+k]

    const int tid  = threadIdx.x;
    const int row0 = blockIdx.x * TM;

    // W transpose load: LDG coalesced; STS stride 132 (4-way conflict, one-time)
    for (int i = tid; i < DIMC * DIMC; i += 256) {
        int col = i >> 7, k = i & 127;
        Wt[k * SWT + col] = W[i];
    }
    // A tile transpose load: LDG coalesced; STS stride 68 (4-way conflict, one-time)
    for (int i = tid; i < TM * DIMC; i += 256) {
        int r = i >> 7, c = i & 127;
        int gr = row0 + r;
        AsT[c * SAT + r] = (gr < M) ? A[(size_t)gr * DIMC + c] : 0.0f;
    }
    __syncthreads();

    // Micro-tile: 4 rows x 8 cols per thread.
    // rows: rr..rr+3 (one LDS.128 from AsT); cols: 4*tc + 64*j, j=0..1 (two LDS.128 from Wt)
    const int tg = tid >> 4;       // 0..15
    const int tc = tid & 15;       // 0..15
    const int rr = tg * 4;
    const int cc = tc * 4;

    unsigned long long acc[4][2][2];   // [row][j][pair] as f32x2
#pragma unroll
    for (int i = 0; i < 4; ++i)
#pragma unroll
        for (int j = 0; j < 2; ++j) { acc[i][j][0] = 0ULL; acc[i][j][1] = 0ULL; }

    // k+1 register double-buffer to hide LDS latency
    float4     a_nx  = *reinterpret_cast<const float4*>(&AsT[rr]);
    ulonglong2 w0_nx = *reinterpret_cast<const ulonglong2*>(&Wt[cc]);
    ulonglong2 w1_nx = *reinterpret_cast<const ulonglong2*>(&Wt[cc + 64]);

#pragma unroll 4
    for (int k = 0; k < DIMC; ++k) {
        float4     a  = a_nx;
        ulonglong2 w0 = w0_nx;
        ulonglong2 w1 = w1_nx;

        int kn = (k + 1 < DIMC) ? (k + 1) : k;   // last iter reloads k (harmless)
        a_nx  = *reinterpret_cast<const float4*>(&AsT[kn * SAT + rr]);
        w0_nx = *reinterpret_cast<const ulonglong2*>(&Wt[kn * SWT + cc]);
        w1_nx = *reinterpret_cast<const ulonglong2*>(&Wt[kn * SWT + cc + 64]);

        unsigned long long aP[4];
        PACK_DUP_F32X2(aP[0], a.x);
        PACK_DUP_F32X2(aP[1], a.y);
        PACK_DUP_F32X2(aP[2], a.z);
        PACK_DUP_F32X2(aP[3], a.w);

#pragma unroll
        for (int i = 0; i < 4; ++i) {
            FMA_F32X2(acc[i][0][0], aP[i], w0.x);
            FMA_F32X2(acc[i][0][1], aP[i], w0.y);
            FMA_F32X2(acc[i][1][0], aP[i], w1.x);
            FMA_F32X2(acc[i][1][1], aP[i], w1.y);
        }
    }

    const float e = (n_init != nullptr) ? eps[0] : 0.0f;
#pragma unroll
    for (int i = 0; i < 4; ++i) {
        int gr = row0 + rr + i;
        if (gr >= M) continue;
#pragma unroll
        for (int j = 0; j < 2; ++j) {
            int c = cc + 64 * j;
            float v0, v1, v2, v3;
            UNPACK_F32X2(v0, v1, acc[i][j][0]);
            UNPACK_F32X2(v2, v3, acc[i][j][1]);
            v0 = fmaxf(v0 + bias[c + 0], 0.0f);
            v1 = fmaxf(v1 + bias[c + 1], 0.0f);
            v2 = fmaxf(v2 + bias[c + 2], 0.0f);
            v3 = fmaxf(v3 + bias[c + 3], 0.0f);
            *reinterpret_cast<float4*>(&out[(size_t)gr * DIMC + c])
                = make_float4(v0, v1, v2, v3);
            if (n_init)
                *reinterpret_cast<float4*>(&n_init[(size_t)gr * DIMC + c])
                    = make_float4(1.0f + e * v0, 1.0f + e * v1,
                                  1.0f + e * v2, 1.0f + e * v3);
        }
    }
}

// One warp per edge: gather h[src] (float4 per lane), atomicAdd(float4) to n[dst]
// src/dst are int32 (JAX x64 disabled).
__global__ __launch_bounds__(256) void scatter_kernel(
    const float* __restrict__ h, const int* __restrict__ src,
    const int* __restrict__ dst, float* __restrict__ nacc, int E)
{
    int gid  = blockIdx.x * blockDim.x + threadIdx.x;
    int e    = gid >> 5;
    int lane = gid & 31;
    if (e >= E) return;

    int s = src[e];
    int d = dst[e];

    float4 v = reinterpret_cast<const float4*>(h + (size_t)s * DIMC)[lane];
    atomicAdd(reinterpret_cast<float4*>(nacc + (size_t)d * DIMC) + lane, v);
}

extern "C" void kernel_launch(void* const* d_in, const int* in_sizes, int n_in,
                              void* d_out, int out_size)
{
    const float* feats = (const float*)d_in[0];
    const int*   src   = (const int*)d_in[1];
    const int*   dst   = (const int*)d_in[2];
    const float* W_f   = (const float*)d_in[3];
    const float* b_f   = (const float*)d_in[4];
    const float* W_phy = (const float*)d_in[5];
    const float* b_phy = (const float*)d_in[6];
    const float* eps   = (const float*)d_in[7];
    float*       out   = (float*)d_out;

    const int M = in_sizes[0] / DIMC;   // 50000
    const int E = in_sizes[1];          // 625000

    float *h_ptr, *n_ptr;
    cudaGetSymbolAddress((void**)&h_ptr, g_h);
    cudaGetSymbolAddress((void**)&n_ptr, g_n);

    const size_t smem = (size_t)(DIMC * SWT + DIMC * SAT) * sizeof(float);  // 102,400 B
    cudaFuncSetAttribute(gemm_relu_kernel,
                         cudaFuncAttributeMaxDynamicSharedMemorySize, (int)smem);

    const int gblocks = (M + TM - 1) / TM;

    // h = relu(feats W_f^T + b_f); n = 1 + eps*h
    gemm_relu_kernel<<<gblocks, 256, smem>>>(feats, W_f, b_f, h_ptr, n_ptr, eps, M);

    // n += sum_{edges} h[src] at dst
    long long total_threads = (long long)E * 32;
    int sblocks = (int)((total_threads + 255) / 256);
    scatter_kernel<<<sblocks, 256>>>(h_ptr, src, dst, n_ptr, E);

    // out = relu(n W_phy^T + b_phy)
    gemm_relu_kernel<<<gblocks, 256, smem>>>(n_ptr, W_phy, b_phy, out, nullptr, nullptr, M);
}

// round 5
// speedup vs baseline: 1.0377x; 1.0377x over previous
#include <cuda_runtime.h>

#define DIMC 128
#define TM   64
#define SWT  132   // W^T row stride (mult of 4 -> 16B-aligned LDS.128)
#define SAT  68    // A^T row stride (mult of 4 -> 16B-aligned LDS.128)
#define NNODES 50000

// Scratch (no cudaMalloc allowed)
__device__ float g_h[(size_t)NNODES * DIMC];
__device__ float g_n[(size_t)NNODES * DIMC];

#define FMA_F32X2(d, a, b) \
    asm("fma.rn.f32x2 %0, %1, %2, %0;" : "+l"(d) : "l"(a), "l"(b))
#define PACK_DUP_F32X2(d, x) \
    asm("mov.b64 %0, {%1, %1};" : "=l"(d) : "f"(x))
#define UNPACK_F32X2(lo, hi, v) \
    asm("mov.b64 {%0, %1}, %2;" : "=f"(lo), "=f"(hi) : "l"(v))

// C[M,128] = relu(A[M,128] @ W^T + bias); optionally also n_init = 1 + eps*C
__global__ __launch_bounds__(256, 2) void gemm_relu_kernel(
    const float* __restrict__ A, const float* __restrict__ W,
    const float* __restrict__ bias, float* __restrict__ out,
    float* __restrict__ n_init, const float* __restrict__ eps, int M)
{
    extern __shared__ float smem[];
    float* Wt  = smem;               // W^T: [k=128][SWT]  Wt[k*SWT+col] = W[col*128+k]
    float* AsT = smem + DIMC * SWT;  // A^T tile: [k=128][SAT]  AsT[k*SAT+r] = A[(row0+r)*128+k]

    const int tid  = threadIdx.x;
    const int row0 = blockIdx.x * TM;

    // W transpose load: LDG coalesced; STS 4-way conflict (one-time)
    for (int i = tid; i < DIMC * DIMC; i += 256) {
        int col = i >> 7, k = i & 127;
        Wt[k * SWT + col] = W[i];
    }
    // A tile transpose load: LDG coalesced; STS 4-way conflict (one-time)
    for (int i = tid; i < TM * DIMC; i += 256) {
        int r = i >> 7, c = i & 127;
        int gr = row0 + r;
        AsT[c * SAT + r] = (gr < M) ? A[(size_t)gr * DIMC + c] : 0.0f;
    }
    __syncthreads();

    // Micro-tile: 4 rows x 8 cols per thread.
    const int tg = tid >> 4;       // 0..15
    const int tc = tid & 15;       // 0..15
    const int rr = tg * 4;
    const int cc = tc * 4;

    const float* pA = AsT + rr;    // + k*SAT (immediate after unroll)
    const float* pW = Wt  + cc;    // + k*SWT

    unsigned long long acc[4][2][2];   // [row][j][pair] as f32x2
#pragma unroll
    for (int i = 0; i < 4; ++i)
#pragma unroll
        for (int j = 0; j < 2; ++j) { acc[i][j][0] = 0ULL; acc[i][j][1] = 0ULL; }

    // Fully-unrolled, statically-prefetched k-loop: LDS(k+1) issued while FMA(k) runs.
    float4     a_nx  = *reinterpret_cast<const float4*>(pA);
    ulonglong2 w0_nx = *reinterpret_cast<const ulonglong2*>(pW);
    ulonglong2 w1_nx = *reinterpret_cast<const ulonglong2*>(pW + 64);

#pragma unroll
    for (int k = 0; k < DIMC - 1; ++k) {
        float4     a  = a_nx;
        ulonglong2 w0 = w0_nx;
        ulonglong2 w1 = w1_nx;

        a_nx  = *reinterpret_cast<const float4*>(pA + (k + 1) * SAT);
        w0_nx = *reinterpret_cast<const ulonglong2*>(pW + (k + 1) * SWT);
        w1_nx = *reinterpret_cast<const ulonglong2*>(pW + (k + 1) * SWT + 64);

        unsigned long long aP[4];
        PACK_DUP_F32X2(aP[0], a.x);
        PACK_DUP_F32X2(aP[1], a.y);
        PACK_DUP_F32X2(aP[2], a.z);
        PACK_DUP_F32X2(aP[3], a.w);

#pragma unroll
        for (int i = 0; i < 4; ++i) {
            FMA_F32X2(acc[i][0][0], aP[i], w0.x);
            FMA_F32X2(acc[i][0][1], aP[i], w0.y);
            FMA_F32X2(acc[i][1][0], aP[i], w1.x);
            FMA_F32X2(acc[i][1][1], aP[i], w1.y);
        }
    }
    {   // tail k = DIMC-1
        unsigned long long aP[4];
        PACK_DUP_F32X2(aP[0], a_nx.x);
        PACK_DUP_F32X2(aP[1], a_nx.y);
        PACK_DUP_F32X2(aP[2], a_nx.z);
        PACK_DUP_F32X2(aP[3], a_nx.w);
#pragma unroll
        for (int i = 0; i < 4; ++i) {
            FMA_F32X2(acc[i][0][0], aP[i], w0_nx.x);
            FMA_F32X2(acc[i][0][1], aP[i], w0_nx.y);
            FMA_F32X2(acc[i][1][0], aP[i], w1_nx.x);
            FMA_F32X2(acc[i][1][1], aP[i], w1_nx.y);
        }
    }

    const float e = (n_init != nullptr) ? eps[0] : 0.0f;
#pragma unroll
    for (int i = 0; i < 4; ++i) {
        int gr = row0 + rr + i;
        if (gr >= M) continue;
#pragma unroll
        for (int j = 0; j < 2; ++j) {
            int c = cc + 64 * j;
            float v0, v1, v2, v3;
            UNPACK_F32X2(v0, v1, acc[i][j][0]);
            UNPACK_F32X2(v2, v3, acc[i][j][1]);
            v0 = fmaxf(v0 + bias[c + 0], 0.0f);
            v1 = fmaxf(v1 + bias[c + 1], 0.0f);
            v2 = fmaxf(v2 + bias[c + 2], 0.0f);
            v3 = fmaxf(v3 + bias[c + 3], 0.0f);
            *reinterpret_cast<float4*>(&out[(size_t)gr * DIMC + c])
                = make_float4(v0, v1, v2, v3);
            if (n_init)
                *reinterpret_cast<float4*>(&n_init[(size_t)gr * DIMC + c])
                    = make_float4(1.0f + e * v0, 1.0f + e * v1,
                                  1.0f + e * v2, 1.0f + e * v3);
        }
    }
}

// One warp per edge: gather h[src] (float4 per lane), atomicAdd(float4) to n[dst]
// src/dst are int32 (JAX x64 disabled).
__global__ __launch_bounds__(256) void scatter_kernel(
    const float* __restrict__ h, const int* __restrict__ src,
    const int* __restrict__ dst, float* __restrict__ nacc, int E)
{
    int gid  = blockIdx.x * blockDim.x + threadIdx.x;
    int e    = gid >> 5;
    int lane = gid & 31;
    if (e >= E) return;

    int s = src[e];
    int d = dst[e];

    float4 v = reinterpret_cast<const float4*>(h + (size_t)s * DIMC)[lane];
    atomicAdd(reinterpret_cast<float4*>(nacc + (size_t)d * DIMC) + lane, v);
}

extern "C" void kernel_launch(void* const* d_in, const int* in_sizes, int n_in,
                              void* d_out, int out_size)
{
    const float* feats = (const float*)d_in[0];
    const int*   src   = (const int*)d_in[1];
    const int*   dst   = (const int*)d_in[2];
    const float* W_f   = (const float*)d_in[3];
    const float* b_f   = (const float*)d_in[4];
    const float* W_phy = (const float*)d_in[5];
    const float* b_phy = (const float*)d_in[6];
    const float* eps   = (const float*)d_in[7];
    float*       out   = (float*)d_out;

    const int M = in_sizes[0] / DIMC;   // 50000
    const int E = in_sizes[1];          // 625000

    float *h_ptr, *n_ptr;
    cudaGetSymbolAddress((void**)&h_ptr, g_h);
    cudaGetSymbolAddress((void**)&n_ptr, g_n);

    const size_t smem = (size_t)(DIMC * SWT + DIMC * SAT) * sizeof(float);  // 102,400 B
    cudaFuncSetAttribute(gemm_relu_kernel,
                         cudaFuncAttributeMaxDynamicSharedMemorySize, (int)smem);

    const int gblocks = (M + TM - 1) / TM;

    // h = relu(feats W_f^T + b_f); n = 1 + eps*h
    gemm_relu_kernel<<<gblocks, 256, smem>>>(feats, W_f, b_f, h_ptr, n_ptr, eps, M);

    // n += sum_{edges} h[src] at dst
    long long total_threads = (long long)E * 32;
    int sblocks = (int)((total_threads + 255) / 256);
    scatter_kernel<<<sblocks, 256>>>(h_ptr, src, dst, n_ptr, E);

    // out = relu(n W_phy^T + b_phy)
    gemm_relu_kernel<<<gblocks, 256, smem>>>(n_ptr, W_phy, b_phy, out, nullptr, nullptr, M);
}